// round 9
// baseline (speedup 1.0000x reference)
#include <cuda_runtime.h>
#include <cstdint>
#include <math.h>

#define NN 50000
#define EE 400000
#define HC 128
#define EDIM 16
#define BN_EPS 1e-5f

// ---------------- scratch (device globals; no allocation allowed) ----------------
__device__ float g_Q[(size_t)NN * HC];
__device__ float g_K[(size_t)NN * HC];
__device__ float g_V[(size_t)NN * HC];
__device__ float g_S[(size_t)NN * HC];        // skip; overwritten with y = attn + skip
__device__ float g_Asp[(size_t)NN * 256];     // input split: hi/lo interleaved
__device__ float g_Wsp[4][128 * 256];         // 4 weight matrices split, hi/lo interleaved

__device__ int g_deg[NN];
__device__ int g_cur[NN];
__device__ int g_off[NN + 1];
__device__ int g_eids[EE];
__device__ int g_bsum[256];
__device__ int g_boff[256];
__device__ float g_bnsum[HC];
__device__ float g_bnsq[HC];

// ---------------- tf32 split helpers ----------------
__device__ __forceinline__ void tf32_split(float a, float& h, float& l) {
    unsigned hb, lb;
    asm("cvt.rna.tf32.f32 %0, %1;" : "=r"(hb) : "f"(a));
    float hf = __uint_as_float(hb);
    float r = a - hf;
    asm("cvt.rna.tf32.f32 %0, %1;" : "=r"(lb) : "f"(r));
    h = hf;
    l = __uint_as_float(lb);
}

__global__ void k_splitA(const float* __restrict__ A, float* __restrict__ Asp, int n2) {
    int i = blockIdx.x * blockDim.x + threadIdx.x;
    if (i >= n2) return;
    float2 v = ((const float2*)A)[i];
    float hx, lx, hy, ly;
    tf32_split(v.x, hx, lx);
    tf32_split(v.y, hy, ly);
    ((float4*)Asp)[i] = make_float4(hx, lx, hy, ly);
}

__global__ void k_splitW(const float* __restrict__ w0, const float* __restrict__ w1,
                         const float* __restrict__ w2, const float* __restrict__ w3) {
    int i = blockIdx.x * blockDim.x + threadIdx.x;   // 0 .. 4*8192-1
    if (i >= 4 * 8192) return;
    int which = i >> 13;
    int j = i & 8191;
    const float* w = which == 0 ? w0 : which == 1 ? w1 : which == 2 ? w2 : w3;
    float2 v = ((const float2*)w)[j];
    float hx, lx, hy, ly;
    tf32_split(v.x, hx, lx);
    tf32_split(v.y, hy, ly);
    ((float4*)&g_Wsp[which][0])[j] = make_float4(hx, lx, hy, ly);
}

// ---------------- CSR build ----------------
__global__ void k_zero_csr() {
    int i = blockIdx.x * blockDim.x + threadIdx.x;
    if (i < NN) { g_deg[i] = 0; g_cur[i] = 0; }
}

__global__ void k_hist(const int* __restrict__ dst) {
    int e = blockIdx.x * blockDim.x + threadIdx.x;
    if (e < EE) atomicAdd(&g_deg[dst[e]], 1);
}

__global__ void k_scan1() {
    __shared__ int sh[256];
    int tid = threadIdx.x;
    int i = blockIdx.x * 256 + tid;
    int v = (i < NN) ? g_deg[i] : 0;
    sh[tid] = v;
    __syncthreads();
    for (int o = 1; o < 256; o <<= 1) {
        int t = (tid >= o) ? sh[tid - o] : 0;
        __syncthreads();
        sh[tid] += t;
        __syncthreads();
    }
    if (i < NN) g_off[i] = sh[tid] - v;
    if (tid == 255) g_bsum[blockIdx.x] = sh[255];
}

__global__ void k_scan2(int nb) {
    __shared__ int sh[256];
    int tid = threadIdx.x;
    int v = (tid < nb) ? g_bsum[tid] : 0;
    sh[tid] = v;
    __syncthreads();
    for (int o = 1; o < 256; o <<= 1) {
        int t = (tid >= o) ? sh[tid - o] : 0;
        __syncthreads();
        sh[tid] += t;
        __syncthreads();
    }
    g_boff[tid] = sh[tid] - v;
}

__global__ void k_scan3() {
    int i = blockIdx.x * 256 + threadIdx.x;
    if (i < NN) g_off[i] += g_boff[blockIdx.x];
    if (i == 0) g_off[NN] = EE;
}

__global__ void k_fill(const int* __restrict__ dst) {
    int e = blockIdx.x * blockDim.x + threadIdx.x;
    if (e < EE) {
        int d = dst[e];
        int pos = g_off[d] + atomicAdd(&g_cur[d], 1);
        g_eids[pos] = e;
    }
}

// ---------------- fused 3xTF32 tensor-core GEMM (Q,K,V,S in one launch) ----------------
#define SA2 72    // A smem row stride in floats (32*2 + 8 pad)
#define SB2 264   // B smem row stride in floats (128*2 + 8 pad)
#define G4_SMEM ((128 * SA2 + 32 * SB2) * 4)   // 70656 bytes

__device__ __forceinline__ void cpa16(unsigned int dst, const void* src, int bytes) {
    asm volatile("cp.async.ca.shared.global [%0], [%1], 16, %2;\n"
                 :: "r"(dst), "l"(src), "r"(bytes));
}

__device__ __forceinline__ void mma8(float* d, unsigned a0, unsigned a1, unsigned a2,
                                     unsigned a3, unsigned b0, unsigned b1) {
    asm volatile(
        "mma.sync.aligned.m16n8k8.row.col.f32.tf32.tf32.f32 "
        "{%0,%1,%2,%3}, {%4,%5,%6,%7}, {%8,%9}, {%0,%1,%2,%3};\n"
        : "+f"(d[0]), "+f"(d[1]), "+f"(d[2]), "+f"(d[3])
        : "r"(a0), "r"(a1), "r"(a2), "r"(a3), "r"(b0), "r"(b1));
}

__global__ void __launch_bounds__(256, 2) k_gemm4(
    const float* __restrict__ Asp,
    const float* __restrict__ b0p, const float* __restrict__ b1p,
    const float* __restrict__ b2p, const float* __restrict__ b3p,
    float* __restrict__ o0p, float* __restrict__ o1p,
    float* __restrict__ o2p, float* __restrict__ o3p, int M)
{
    extern __shared__ float sm[];
    float* As = sm;               // [128][SA2]
    float* Bs = sm + 128 * SA2;   // [32][SB2]
    unsigned int As_u = (unsigned int)__cvta_generic_to_shared(As);
    unsigned int Bs_u = (unsigned int)__cvta_generic_to_shared(Bs);

    int tid = threadIdx.x;
    int wid = tid >> 5, lane = tid & 31;
    int g = lane >> 2, tig = lane & 3;
    int m0 = (wid & 1) * 64;
    int n0 = (wid >> 1) * 32;
    int brow = blockIdx.x * 128;
    int which = blockIdx.y;

    const float* W = &g_Wsp[which][0];
    const float* bias = which == 0 ? b0p : which == 1 ? b1p : which == 2 ? b2p : b3p;
    float* C = which == 0 ? o0p : which == 1 ? o1p : which == 2 ? o2p : o3p;

    float acc[4][4][4];
#pragma unroll
    for (int i = 0; i < 4; i++)
#pragma unroll
        for (int j = 0; j < 4; j++)
#pragma unroll
            for (int r = 0; r < 4; r++) acc[i][j][r] = 0.f;

    for (int k0 = 0; k0 < 128; k0 += 32) {
#pragma unroll
        for (int j = 0; j < 8; j++) {
            int idx = tid + j * 256;
            int row = idx >> 4;
            int c4 = idx & 15;
            int grow = brow + row;
            int nb = (grow < M) ? 16 : 0;
            cpa16(As_u + (row * SA2 + c4 * 4) * 4,
                  &Asp[(size_t)grow * 256 + k0 * 2 + c4 * 4], nb);
        }
#pragma unroll
        for (int j = 0; j < 8; j++) {
            int idx = tid + j * 256;
            int row = idx >> 6;
            int c4 = idx & 63;
            cpa16(Bs_u + (row * SB2 + c4 * 4) * 4,
                  &W[(size_t)(k0 + row) * 256 + c4 * 4], 16);
        }
        asm volatile("cp.async.commit_group;\n");
        asm volatile("cp.async.wait_group 0;\n");
        __syncthreads();

#pragma unroll
        for (int ks = 0; ks < 4; ks++) {
            int kk = ks * 8;
            // load ALL B fragments first (16 regs live), then stream A per-mf (8 regs)
            unsigned bh[4][2], bl[4][2];
#pragma unroll
            for (int nf = 0; nf < 4; nf++) {
                const float* bp = &Bs[(kk + tig) * SB2 + 2 * (n0 + nf * 8 + g)];
                float2 w0 = *(const float2*)bp;
                float2 w1 = *(const float2*)(bp + 4 * SB2);
                bh[nf][0] = __float_as_uint(w0.x); bl[nf][0] = __float_as_uint(w0.y);
                bh[nf][1] = __float_as_uint(w1.x); bl[nf][1] = __float_as_uint(w1.y);
            }
#pragma unroll
            for (int mf = 0; mf < 4; mf++) {
                const float* ab = &As[(m0 + mf * 16 + g) * SA2 + 2 * (kk + tig)];
                float2 v0 = *(const float2*)ab;
                float2 v2 = *(const float2*)(ab + 8);
                float2 v1 = *(const float2*)(ab + 8 * SA2);
                float2 v3 = *(const float2*)(ab + 8 * SA2 + 8);
                unsigned a0h = __float_as_uint(v0.x), a0l = __float_as_uint(v0.y);
                unsigned a1h = __float_as_uint(v1.x), a1l = __float_as_uint(v1.y);
                unsigned a2h = __float_as_uint(v2.x), a2l = __float_as_uint(v2.y);
                unsigned a3h = __float_as_uint(v3.x), a3l = __float_as_uint(v3.y);
#pragma unroll
                for (int nf = 0; nf < 4; nf++) {
                    float* d = acc[mf][nf];
                    mma8(d, a0h, a1h, a2h, a3h, bh[nf][0], bh[nf][1]);
                    mma8(d, a0h, a1h, a2h, a3h, bl[nf][0], bl[nf][1]);
                    mma8(d, a0l, a1l, a2l, a3l, bh[nf][0], bh[nf][1]);
                }
            }
        }
        __syncthreads();
    }

#pragma unroll
    for (int nf = 0; nf < 4; nf++) {
        int col = n0 + nf * 8 + tig * 2;
        float b0v = bias[col], b1v = bias[col + 1];
#pragma unroll
        for (int mf = 0; mf < 4; mf++) {
            int r0 = brow + m0 + mf * 16 + g;
            float* d = acc[mf][nf];
            if (r0 < M)
                *(float2*)&C[(size_t)r0 * 128 + col] = make_float2(d[0] + b0v, d[1] + b1v);
            if (r0 + 8 < M)
                *(float2*)&C[(size_t)(r0 + 8) * 128 + col] = make_float2(d[2] + b0v, d[3] + b1v);
        }
    }
}

// ---------------- edge attention v2: factored edge embedding ----------------
// one warp per dst node. lane l owns channels [4l,4l+4), head h=l>>3, sub=l&7.
// a = q·k/√C + EA·P[dst]/√C  with P[h][d] = Σ_c q[h,c]·EW[d,hc]  (per-node setup)
// Σ α·(v+e) = (accV + G@EW)/s with G[h][d] = Σ pe·EA[d] (2 regs/lane, same rescale)
__global__ void __launch_bounds__(256) k_edge(
    const float* __restrict__ EA,   // [E,16]
    const float* __restrict__ EW,   // [16,128]
    const int* __restrict__ src)
{
    __shared__ __align__(16) float4 ews[16 * 32];
    for (int i = threadIdx.x; i < 16 * 32; i += 256)
        ews[i] = ((const float4*)EW)[i];
    __syncthreads();

    int warp = (blockIdx.x * 256 + threadIdx.x) >> 5;
    int lane = threadIdx.x & 31;
    if (warp >= NN) return;
    int node = warp;
    int sub = lane & 7;
    int beg = g_off[node], end = g_off[node + 1];

    float4 qv = *(const float4*)&g_Q[(size_t)node * HC + lane * 4];

    // per-node setup: P[h][d] for this lane's (d0,d1) = (2*sub, 2*sub+1)
    float p0 = 0.f, p1 = 0.f;
#pragma unroll
    for (int d = 0; d < EDIM; d++) {
        float4 wc = ews[d * 32 + lane];
        float part = qv.x * wc.x + qv.y * wc.y + qv.z * wc.z + qv.w * wc.w;
        part += __shfl_xor_sync(0xffffffffu, part, 1);
        part += __shfl_xor_sync(0xffffffffu, part, 2);
        part += __shfl_xor_sync(0xffffffffu, part, 4);
        if (d == 2 * sub) p0 = part;
        if (d == 2 * sub + 1) p1 = part;
    }

    float m = -1e30f, s = 0.f;
    float ax = 0.f, ay = 0.f, az = 0.f, aw = 0.f;
    float g0 = 0.f, g1 = 0.f;

    for (int p = beg; p < end; p++) {
        int e = g_eids[p];
        int sn = src[e];
        float2 ea2 = *(const float2*)&EA[(size_t)e * EDIM + 2 * sub];
        float4 kv = *(const float4*)&g_K[(size_t)sn * HC + lane * 4];

        float part = qv.x * kv.x + qv.y * kv.y + qv.z * kv.z + qv.w * kv.w
                   + ea2.x * p0 + ea2.y * p1;
        part += __shfl_xor_sync(0xffffffffu, part, 1);
        part += __shfl_xor_sync(0xffffffffu, part, 2);
        part += __shfl_xor_sync(0xffffffffu, part, 4);
        float a = part * 0.17677669529663687f;   // 1/sqrt(32)

        float nm = fmaxf(m, a);
        float sc = __expf(m - nm);
        float pe = __expf(a - nm);
        s = s * sc + pe;

        float4 vv = *(const float4*)&g_V[(size_t)sn * HC + lane * 4];
        ax = ax * sc + pe * vv.x;
        ay = ay * sc + pe * vv.y;
        az = az * sc + pe * vv.z;
        aw = aw * sc + pe * vv.w;
        g0 = g0 * sc + pe * ea2.x;
        g1 = g1 * sc + pe * ea2.y;
        m = nm;
    }

    // epilogue: e-contribution = G[h][:] @ EW[:, lane channels]
    float ex = 0.f, ey = 0.f, ez = 0.f, ew_ = 0.f;
    int base = lane & ~7;
#pragma unroll
    for (int j = 0; j < 8; j++) {
        float gg0 = __shfl_sync(0xffffffffu, g0, base + j);
        float gg1 = __shfl_sync(0xffffffffu, g1, base + j);
        float4 w0 = ews[(2 * j) * 32 + lane];
        float4 w1 = ews[(2 * j + 1) * 32 + lane];
        ex += gg0 * w0.x + gg1 * w1.x;
        ey += gg0 * w0.y + gg1 * w1.y;
        ez += gg0 * w0.z + gg1 * w1.z;
        ew_ += gg0 * w0.w + gg1 * w1.w;
    }

    float inv = (end > beg) ? (1.f / s) : 0.f;
    size_t o = (size_t)node * HC + lane * 4;
    float4 sv = *(const float4*)&g_S[o];
    float4 y = make_float4((ax + ex) * inv + sv.x, (ay + ey) * inv + sv.y,
                           (az + ez) * inv + sv.z, (aw + ew_) * inv + sv.w);
    *(float4*)&g_S[o] = y;
}

// ---------------- batchnorm + relu ----------------
__global__ void k_zero_bn() {
    int t = threadIdx.x;
    if (t < HC) { g_bnsum[t] = 0.f; g_bnsq[t] = 0.f; }
}

__global__ void k_bn_reduce() {
    int c = threadIdx.x;
    float sum = 0.f, sq = 0.f;
    for (int n = blockIdx.x; n < NN; n += gridDim.x) {
        float v = g_S[(size_t)n * HC + c];
        sum += v; sq += v * v;
    }
    atomicAdd(&g_bnsum[c], sum);
    atomicAdd(&g_bnsq[c], sq);
}

__global__ void k_bn_apply(const float* __restrict__ gamma,
                           const float* __restrict__ beta,
                           float* __restrict__ out)
{
    int i = blockIdx.x * blockDim.x + threadIdx.x;
    if (i >= NN * HC) return;
    int c = i & 127;
    float mean = g_bnsum[c] * (1.f / NN);
    float var = fmaf(-mean, mean, g_bnsq[c] * (1.f / NN));
    float v = (g_S[i] - mean) * rsqrtf(var + BN_EPS) * gamma[c] + beta[c];
    out[i] = fmaxf(v, 0.f);
}

// ---------------- driver ----------------
extern "C" void kernel_launch(void* const* d_in, const int* in_sizes, int n_in,
                              void* d_out, int out_size)
{
    const float* x  = (const float*)d_in[0];
    const int*   ei = (const int*)d_in[1];
    const float* ea = (const float*)d_in[2];
    const int* src = ei;
    const int* dst = ei + EE;

    float* out = (float*)d_out;
    float* x1 = out;
    float* x2 = out + (size_t)NN * HC;

    float *Q, *K, *V, *S, *Asp;
    cudaGetSymbolAddress((void**)&Q, g_Q);
    cudaGetSymbolAddress((void**)&K, g_K);
    cudaGetSymbolAddress((void**)&V, g_V);
    cudaGetSymbolAddress((void**)&S, g_S);
    cudaGetSymbolAddress((void**)&Asp, g_Asp);

    cudaFuncSetAttribute(k_gemm4, cudaFuncAttributeMaxDynamicSharedMemorySize, G4_SMEM);

    const int NB1 = (NN + 255) / 256;
    const dim3 gg4((NN + 127) / 128, 4);
    const int nsplit2 = NN * 64;

    const float* in_ptr = x;
    for (int L = 0; L < 2; L++) {
        int b = 3 + L * 11;
        const float* qw = (const float*)d_in[b + 0];
        const float* qb = (const float*)d_in[b + 1];
        const float* kw = (const float*)d_in[b + 2];
        const float* kb = (const float*)d_in[b + 3];
        const float* vw = (const float*)d_in[b + 4];
        const float* vb = (const float*)d_in[b + 5];
        const float* ew = (const float*)d_in[b + 6];
        const float* sw = (const float*)d_in[b + 7];
        const float* sb = (const float*)d_in[b + 8];
        const float* bg = (const float*)d_in[b + 9];
        const float* bb = (const float*)d_in[b + 10];

        if (L == 0) {
            // harness issues ~2 launches first; ncu -s 5 lands on OUR index 3 -> k_gemm4
            k_splitA<<<(nsplit2 + 255) / 256, 256>>>(in_ptr, Asp, nsplit2);        // 0
            k_splitW<<<128, 256>>>(qw, kw, vw, sw);                                // 1
            k_zero_csr<<<NB1, 256>>>();                                            // 2
            k_gemm4<<<gg4, 256, G4_SMEM>>>(Asp, qb, kb, vb, sb, Q, K, V, S, NN);   // 3 (profiled)
            k_hist<<<(EE + 255) / 256, 256>>>(dst);
            k_scan1<<<NB1, 256>>>();
            k_scan2<<<1, 256>>>(NB1);
            k_scan3<<<NB1, 256>>>();
            k_fill<<<(EE + 255) / 256, 256>>>(dst);
        } else {
            k_splitA<<<(nsplit2 + 255) / 256, 256>>>(in_ptr, Asp, nsplit2);
            k_splitW<<<128, 256>>>(qw, kw, vw, sw);
            k_gemm4<<<gg4, 256, G4_SMEM>>>(Asp, qb, kb, vb, sb, Q, K, V, S, NN);
        }

        k_edge<<<(NN * 32 + 255) / 256, 256>>>(ea, ew, src);

        k_zero_bn<<<1, 128>>>();
        k_bn_reduce<<<512, 128>>>();
        k_bn_apply<<<(NN * HC + 255) / 256, 256>>>(bg, bb, (L == 0) ? x1 : x2);

        in_ptr = x1;
    }
}

// round 10
// speedup vs baseline: 1.2282x; 1.2282x over previous
#include <cuda_runtime.h>
#include <cuda_bf16.h>
#include <cstdint>
#include <math.h>

#define NN 50000
#define EE 400000
#define HC 128
#define EDIM 16
#define BN_EPS 1e-5f

// ---------------- scratch (device globals; no allocation allowed) ----------------
__device__ float g_Q[(size_t)NN * HC];
__device__ float g_K[(size_t)NN * HC];
__device__ float g_V[(size_t)NN * HC];
__device__ float g_S[(size_t)NN * HC];   // skip; overwritten with y = attn + skip

// bf16 hi/lo pre-split operands, k-quad-permuted: pos(k)= (k>>4)*16+((k&7)>>1)*4+((k&1)+((k>>3)&1)*2)
__device__ __nv_bfloat16 g_Ah[(size_t)NN * HC];
__device__ __nv_bfloat16 g_Al[(size_t)NN * HC];
__device__ __nv_bfloat16 g_Wth[4][HC * HC];   // W transposed: [n][k-permuted]
__device__ __nv_bfloat16 g_Wtl[4][HC * HC];

__device__ int g_deg[NN];
__device__ int g_cur[NN];
__device__ int g_off[NN + 1];
__device__ int g_eids[EE];
__device__ int g_bsum[256];
__device__ int g_boff[256];
__device__ float g_bnsum[HC];
__device__ float g_bnsq[HC];

// ---------------- bf16 hi/lo split helpers ----------------
__device__ __forceinline__ void bf16_split(float x, unsigned short& h, unsigned short& l) {
    __nv_bfloat16 hb = __float2bfloat16_rn(x);
    __nv_bfloat16 lb = __float2bfloat16_rn(x - __bfloat162float(hb));
    h = __bfloat16_as_ushort(hb);
    l = __bfloat16_as_ushort(lb);
}

// pre-split A [N][128] fp32 -> g_Ah/g_Al bf16 quads (k-permuted).
// thread i: row = i>>5, qi = i&31; quad ks = {16s+2t, +1, 16s+8+2t, +1}, s=qi>>2, t=qi&3
__global__ void k_splitA(const float* __restrict__ A, int nthr) {
    int i = blockIdx.x * blockDim.x + threadIdx.x;
    if (i >= nthr) return;
    int row = i >> 5, qi = i & 31;
    int s = qi >> 2, t = qi & 3;
    const float* ap = A + (size_t)row * HC;
    float2 vlo = *(const float2*)&ap[16 * s + 2 * t];
    float2 vhi = *(const float2*)&ap[16 * s + 8 + 2 * t];
    unsigned short h0, l0, h1, l1, h2, l2, h3, l3;
    bf16_split(vlo.x, h0, l0);
    bf16_split(vlo.y, h1, l1);
    bf16_split(vhi.x, h2, l2);
    bf16_split(vhi.y, h3, l3);
    uint2 ph = make_uint2((unsigned)h0 | ((unsigned)h1 << 16),
                          (unsigned)h2 | ((unsigned)h3 << 16));
    uint2 pl = make_uint2((unsigned)l0 | ((unsigned)l1 << 16),
                          (unsigned)l2 | ((unsigned)l3 << 16));
    *(uint2*)&g_Ah[(size_t)row * HC + qi * 4] = ph;
    *(uint2*)&g_Al[(size_t)row * HC + qi * 4] = pl;
}

// pre-split + transpose the 4 weights: Wt[n][k-permuted] from W[k][n]
__global__ void k_splitW(const float* __restrict__ w0, const float* __restrict__ w1,
                         const float* __restrict__ w2, const float* __restrict__ w3) {
    int i = blockIdx.x * blockDim.x + threadIdx.x;   // 0 .. 4*128*32-1
    if (i >= 4 * 128 * 32) return;
    int which = i >> 12;
    int rem = i & 4095;
    int n = rem >> 5, qi = rem & 31;
    int s = qi >> 2, t = qi & 3;
    const float* w = which == 0 ? w0 : which == 1 ? w1 : which == 2 ? w2 : w3;
    float x0 = w[(size_t)(16 * s + 2 * t) * HC + n];
    float x1 = w[(size_t)(16 * s + 2 * t + 1) * HC + n];
    float x2 = w[(size_t)(16 * s + 8 + 2 * t) * HC + n];
    float x3 = w[(size_t)(16 * s + 9 + 2 * t) * HC + n];
    unsigned short h0, l0, h1, l1, h2, l2, h3, l3;
    bf16_split(x0, h0, l0);
    bf16_split(x1, h1, l1);
    bf16_split(x2, h2, l2);
    bf16_split(x3, h3, l3);
    uint2 ph = make_uint2((unsigned)h0 | ((unsigned)h1 << 16),
                          (unsigned)h2 | ((unsigned)h3 << 16));
    uint2 pl = make_uint2((unsigned)l0 | ((unsigned)l1 << 16),
                          (unsigned)l2 | ((unsigned)l3 << 16));
    *(uint2*)&g_Wth[which][(size_t)n * HC + qi * 4] = ph;
    *(uint2*)&g_Wtl[which][(size_t)n * HC + qi * 4] = pl;
}

// ---------------- CSR build ----------------
__global__ void k_zero_csr() {
    int i = blockIdx.x * blockDim.x + threadIdx.x;
    if (i < NN) { g_deg[i] = 0; g_cur[i] = 0; }
}

__global__ void k_hist(const int* __restrict__ dst) {
    int e = blockIdx.x * blockDim.x + threadIdx.x;
    if (e < EE) atomicAdd(&g_deg[dst[e]], 1);
}

__global__ void k_scan1() {
    __shared__ int sh[256];
    int tid = threadIdx.x;
    int i = blockIdx.x * 256 + tid;
    int v = (i < NN) ? g_deg[i] : 0;
    sh[tid] = v;
    __syncthreads();
    for (int o = 1; o < 256; o <<= 1) {
        int t = (tid >= o) ? sh[tid - o] : 0;
        __syncthreads();
        sh[tid] += t;
        __syncthreads();
    }
    if (i < NN) g_off[i] = sh[tid] - v;
    if (tid == 255) g_bsum[blockIdx.x] = sh[255];
}

__global__ void k_scan2(int nb) {
    __shared__ int sh[256];
    int tid = threadIdx.x;
    int v = (tid < nb) ? g_bsum[tid] : 0;
    sh[tid] = v;
    __syncthreads();
    for (int o = 1; o < 256; o <<= 1) {
        int t = (tid >= o) ? sh[tid - o] : 0;
        __syncthreads();
        sh[tid] += t;
        __syncthreads();
    }
    g_boff[tid] = sh[tid] - v;
}

__global__ void k_scan3() {
    int i = blockIdx.x * 256 + threadIdx.x;
    if (i < NN) g_off[i] += g_boff[blockIdx.x];
    if (i == 0) g_off[NN] = EE;
}

__global__ void k_fill(const int* __restrict__ dst) {
    int e = blockIdx.x * blockDim.x + threadIdx.x;
    if (e < EE) {
        int d = dst[e];
        int pos = g_off[d] + atomicAdd(&g_cur[d], 1);
        g_eids[pos] = e;
    }
}

// ---------------- fused bf16x2 tensor-core GEMM (Q,K,V,S in one launch) ----------------
// C = A@W + bias via (ah+al)(bh+bl) ~= ah.bh + ah.bl + al.bh, mma.m16n8k16.bf16
// BM=128, BN=128, BK=64 x 2 chunks. 8 warps, warp tile 64x32. 2 CTAs/SM.
#define SROW 80   // smem row stride in bf16 (64 data + 16 pad = 160B; conflict-free LDS.64)
#define PLANE (128 * SROW)
#define G4_SMEM (4 * PLANE * 2)   // 81920 bytes

__device__ __forceinline__ void cpa16(unsigned int dst, const void* src, int bytes) {
    asm volatile("cp.async.ca.shared.global [%0], [%1], 16, %2;\n"
                 :: "r"(dst), "l"(src), "r"(bytes));
}

__device__ __forceinline__ void mma16(float* d, unsigned a0, unsigned a1, unsigned a2,
                                      unsigned a3, unsigned b0, unsigned b1) {
    asm volatile(
        "mma.sync.aligned.m16n8k16.row.col.f32.bf16.bf16.f32 "
        "{%0,%1,%2,%3}, {%4,%5,%6,%7}, {%8,%9}, {%0,%1,%2,%3};\n"
        : "+f"(d[0]), "+f"(d[1]), "+f"(d[2]), "+f"(d[3])
        : "r"(a0), "r"(a1), "r"(a2), "r"(a3), "r"(b0), "r"(b1));
}

__global__ void __launch_bounds__(256, 2) k_gemm4(
    const float* __restrict__ b0p, const float* __restrict__ b1p,
    const float* __restrict__ b2p, const float* __restrict__ b3p,
    float* __restrict__ o0p, float* __restrict__ o1p,
    float* __restrict__ o2p, float* __restrict__ o3p, int M)
{
    extern __shared__ __nv_bfloat16 sm[];
    __nv_bfloat16* Ah = sm;
    __nv_bfloat16* Al = sm + PLANE;
    __nv_bfloat16* Bh = sm + 2 * PLANE;
    __nv_bfloat16* Bl = sm + 3 * PLANE;
    unsigned int Ah_u = (unsigned int)__cvta_generic_to_shared(Ah);
    unsigned int Al_u = (unsigned int)__cvta_generic_to_shared(Al);
    unsigned int Bh_u = (unsigned int)__cvta_generic_to_shared(Bh);
    unsigned int Bl_u = (unsigned int)__cvta_generic_to_shared(Bl);

    int tid = threadIdx.x;
    int wid = tid >> 5, lane = tid & 31;
    int g = lane >> 2, tig = lane & 3;
    int m0 = (wid & 1) * 64;
    int n0 = (wid >> 1) * 32;
    int brow = blockIdx.x * 128;
    int which = blockIdx.y;

    const __nv_bfloat16* Wh = &g_Wth[which][0];
    const __nv_bfloat16* Wl = &g_Wtl[which][0];
    const float* bias = which == 0 ? b0p : which == 1 ? b1p : which == 2 ? b2p : b3p;
    float* C = which == 0 ? o0p : which == 1 ? o1p : which == 2 ? o2p : o3p;

    float acc[4][4][4];
#pragma unroll
    for (int i = 0; i < 4; i++)
#pragma unroll
        for (int j = 0; j < 4; j++)
#pragma unroll
            for (int r = 0; r < 4; r++) acc[i][j][r] = 0.f;

    for (int k0 = 0; k0 < 128; k0 += 64) {
        // A planes: 128 rows x 64 bf16 (128B) = 8 x 16B per row
#pragma unroll
        for (int j = 0; j < 4; j++) {
            int idx = tid + j * 256;          // 0..1023
            int row = idx >> 3;
            int c = idx & 7;
            int grow = brow + row;
            int nb = (grow < M) ? 16 : 0;
            unsigned off = (unsigned)(row * SROW + c * 8) * 2;
            const __nv_bfloat16* sA = &g_Ah[(size_t)grow * HC + k0 + c * 8];
            const __nv_bfloat16* sAl = &g_Al[(size_t)grow * HC + k0 + c * 8];
            cpa16(Ah_u + off, sA, nb);
            cpa16(Al_u + off, sAl, nb);
        }
        // B planes: 128 n-rows x 64 bf16
#pragma unroll
        for (int j = 0; j < 4; j++) {
            int idx = tid + j * 256;
            int row = idx >> 3;
            int c = idx & 7;
            unsigned off = (unsigned)(row * SROW + c * 8) * 2;
            cpa16(Bh_u + off, &Wh[(size_t)row * HC + k0 + c * 8], 16);
            cpa16(Bl_u + off, &Wl[(size_t)row * HC + k0 + c * 8], 16);
        }
        asm volatile("cp.async.commit_group;\n");
        asm volatile("cp.async.wait_group 0;\n");
        __syncthreads();

#pragma unroll
        for (int ks = 0; ks < 4; ks++) {
            int kq = ks * 16 + tig * 4;    // bf16 offset of this thread's quad
            // B fragments for all 4 nf (hi + lo): 8 x LDS.64
            unsigned bh[4][2], bl[4][2];
#pragma unroll
            for (int nf = 0; nf < 4; nf++) {
                int nrow = n0 + nf * 8 + g;
                uint2 vh = *(const uint2*)&Bh[nrow * SROW + kq];
                uint2 vl = *(const uint2*)&Bl[nrow * SROW + kq];
                bh[nf][0] = vh.x; bh[nf][1] = vh.y;
                bl[nf][0] = vl.x; bl[nf][1] = vl.y;
            }
#pragma unroll
            for (int mf = 0; mf < 4; mf++) {
                int ar = (m0 + mf * 16 + g) * SROW + kq;
                uint2 h0 = *(const uint2*)&Ah[ar];             // a0 (row g), a2
                uint2 h1 = *(const uint2*)&Ah[ar + 8 * SROW];  // a1 (row g+8), a3
                uint2 l0 = *(const uint2*)&Al[ar];
                uint2 l1 = *(const uint2*)&Al[ar + 8 * SROW];
#pragma unroll
                for (int nf = 0; nf < 4; nf++) {
                    float* d = acc[mf][nf];
                    mma16(d, h0.x, h1.x, h0.y, h1.y, bh[nf][0], bh[nf][1]);
                    mma16(d, h0.x, h1.x, h0.y, h1.y, bl[nf][0], bl[nf][1]);
                    mma16(d, l0.x, l1.x, l0.y, l1.y, bh[nf][0], bh[nf][1]);
                }
            }
        }
        __syncthreads();
    }

    // epilogue: add bias, store (c0=C[g][2t], c1=C[g][2t+1], c2/c3 row g+8)
#pragma unroll
    for (int nf = 0; nf < 4; nf++) {
        int col = n0 + nf * 8 + tig * 2;
        float b0v = bias[col], b1v = bias[col + 1];
#pragma unroll
        for (int mf = 0; mf < 4; mf++) {
            int r0 = brow + m0 + mf * 16 + g;
            float* d = acc[mf][nf];
            if (r0 < M)
                *(float2*)&C[(size_t)r0 * 128 + col] = make_float2(d[0] + b0v, d[1] + b1v);
            if (r0 + 8 < M)
                *(float2*)&C[(size_t)(r0 + 8) * 128 + col] = make_float2(d[2] + b0v, d[3] + b1v);
        }
    }
}

// ---------------- edge attention v2: factored edge embedding ----------------
__global__ void __launch_bounds__(256) k_edge(
    const float* __restrict__ EA,   // [E,16]
    const float* __restrict__ EW,   // [16,128]
    const int* __restrict__ src)
{
    __shared__ __align__(16) float4 ews[16 * 32];
    for (int i = threadIdx.x; i < 16 * 32; i += 256)
        ews[i] = ((const float4*)EW)[i];
    __syncthreads();

    int warp = (blockIdx.x * 256 + threadIdx.x) >> 5;
    int lane = threadIdx.x & 31;
    if (warp >= NN) return;
    int node = warp;
    int sub = lane & 7;
    int beg = g_off[node], end = g_off[node + 1];

    float4 qv = *(const float4*)&g_Q[(size_t)node * HC + lane * 4];

    float p0 = 0.f, p1 = 0.f;
#pragma unroll
    for (int d = 0; d < EDIM; d++) {
        float4 wc = ews[d * 32 + lane];
        float part = qv.x * wc.x + qv.y * wc.y + qv.z * wc.z + qv.w * wc.w;
        part += __shfl_xor_sync(0xffffffffu, part, 1);
        part += __shfl_xor_sync(0xffffffffu, part, 2);
        part += __shfl_xor_sync(0xffffffffu, part, 4);
        if (d == 2 * sub) p0 = part;
        if (d == 2 * sub + 1) p1 = part;
    }

    float m = -1e30f, s = 0.f;
    float ax = 0.f, ay = 0.f, az = 0.f, aw = 0.f;
    float g0 = 0.f, g1 = 0.f;

    for (int p = beg; p < end; p++) {
        int e = g_eids[p];
        int sn = src[e];
        float2 ea2 = *(const float2*)&EA[(size_t)e * EDIM + 2 * sub];
        float4 kv = *(const float4*)&g_K[(size_t)sn * HC + lane * 4];

        float part = qv.x * kv.x + qv.y * kv.y + qv.z * kv.z + qv.w * kv.w
                   + ea2.x * p0 + ea2.y * p1;
        part += __shfl_xor_sync(0xffffffffu, part, 1);
        part += __shfl_xor_sync(0xffffffffu, part, 2);
        part += __shfl_xor_sync(0xffffffffu, part, 4);
        float a = part * 0.17677669529663687f;   // 1/sqrt(32)

        float nm = fmaxf(m, a);
        float sc = __expf(m - nm);
        float pe = __expf(a - nm);
        s = s * sc + pe;

        float4 vv = *(const float4*)&g_V[(size_t)sn * HC + lane * 4];
        ax = ax * sc + pe * vv.x;
        ay = ay * sc + pe * vv.y;
        az = az * sc + pe * vv.z;
        aw = aw * sc + pe * vv.w;
        g0 = g0 * sc + pe * ea2.x;
        g1 = g1 * sc + pe * ea2.y;
        m = nm;
    }

    float ex = 0.f, ey = 0.f, ez = 0.f, ew_ = 0.f;
    int base = lane & ~7;
#pragma unroll
    for (int j = 0; j < 8; j++) {
        float gg0 = __shfl_sync(0xffffffffu, g0, base + j);
        float gg1 = __shfl_sync(0xffffffffu, g1, base + j);
        float4 w0 = ews[(2 * j) * 32 + lane];
        float4 w1 = ews[(2 * j + 1) * 32 + lane];
        ex += gg0 * w0.x + gg1 * w1.x;
        ey += gg0 * w0.y + gg1 * w1.y;
        ez += gg0 * w0.z + gg1 * w1.z;
        ew_ += gg0 * w0.w + gg1 * w1.w;
    }

    float inv = (end > beg) ? (1.f / s) : 0.f;
    size_t o = (size_t)node * HC + lane * 4;
    float4 sv = *(const float4*)&g_S[o];
    float4 y = make_float4((ax + ex) * inv + sv.x, (ay + ey) * inv + sv.y,
                           (az + ez) * inv + sv.z, (aw + ew_) * inv + sv.w);
    *(float4*)&g_S[o] = y;
}

// ---------------- batchnorm + relu ----------------
__global__ void k_zero_bn() {
    int t = threadIdx.x;
    if (t < HC) { g_bnsum[t] = 0.f; g_bnsq[t] = 0.f; }
}

__global__ void k_bn_reduce() {
    int c = threadIdx.x;
    float sum = 0.f, sq = 0.f;
    for (int n = blockIdx.x; n < NN; n += gridDim.x) {
        float v = g_S[(size_t)n * HC + c];
        sum += v; sq += v * v;
    }
    atomicAdd(&g_bnsum[c], sum);
    atomicAdd(&g_bnsq[c], sq);
}

__global__ void k_bn_apply(const float* __restrict__ gamma,
                           const float* __restrict__ beta,
                           float* __restrict__ out)
{
    int i = blockIdx.x * blockDim.x + threadIdx.x;
    if (i >= NN * HC) return;
    int c = i & 127;
    float mean = g_bnsum[c] * (1.f / NN);
    float var = fmaf(-mean, mean, g_bnsq[c] * (1.f / NN));
    float v = (g_S[i] - mean) * rsqrtf(var + BN_EPS) * gamma[c] + beta[c];
    out[i] = fmaxf(v, 0.f);
}

// ---------------- driver ----------------
extern "C" void kernel_launch(void* const* d_in, const int* in_sizes, int n_in,
                              void* d_out, int out_size)
{
    const float* x  = (const float*)d_in[0];
    const int*   ei = (const int*)d_in[1];
    const float* ea = (const float*)d_in[2];
    const int* src = ei;
    const int* dst = ei + EE;

    float* out = (float*)d_out;
    float* x1 = out;
    float* x2 = out + (size_t)NN * HC;

    float *Q, *K, *V, *S;
    cudaGetSymbolAddress((void**)&Q, g_Q);
    cudaGetSymbolAddress((void**)&K, g_K);
    cudaGetSymbolAddress((void**)&V, g_V);
    cudaGetSymbolAddress((void**)&S, g_S);

    cudaFuncSetAttribute(k_gemm4, cudaFuncAttributeMaxDynamicSharedMemorySize, G4_SMEM);

    const int NB1 = (NN + 255) / 256;
    const dim3 gg4((NN + 127) / 128, 4);
    const int nthrA = NN * 32;

    const float* in_ptr = x;
    for (int L = 0; L < 2; L++) {
        int b = 3 + L * 11;
        const float* qw = (const float*)d_in[b + 0];
        const float* qb = (const float*)d_in[b + 1];
        const float* kw = (const float*)d_in[b + 2];
        const float* kb = (const float*)d_in[b + 3];
        const float* vw = (const float*)d_in[b + 4];
        const float* vb = (const float*)d_in[b + 5];
        const float* ew = (const float*)d_in[b + 6];
        const float* sw = (const float*)d_in[b + 7];
        const float* sb = (const float*)d_in[b + 8];
        const float* bg = (const float*)d_in[b + 9];
        const float* bb = (const float*)d_in[b + 10];

        if (L == 0) {
            // harness issues ~2 launches first; ncu -s 5 lands on OUR index 3 -> k_gemm4
            k_splitA<<<(nthrA + 255) / 256, 256>>>(in_ptr, nthrA);                 // 0
            k_splitW<<<(4 * 128 * 32 + 255) / 256, 256>>>(qw, kw, vw, sw);         // 1
            k_zero_csr<<<NB1, 256>>>();                                            // 2
            k_gemm4<<<gg4, 256, G4_SMEM>>>(qb, kb, vb, sb, Q, K, V, S, NN);        // 3 (profiled)
            k_hist<<<(EE + 255) / 256, 256>>>(dst);
            k_scan1<<<NB1, 256>>>();
            k_scan2<<<1, 256>>>(NB1);
            k_scan3<<<NB1, 256>>>();
            k_fill<<<(EE + 255) / 256, 256>>>(dst);
        } else {
            k_splitA<<<(nthrA + 255) / 256, 256>>>(in_ptr, nthrA);
            k_splitW<<<(4 * 128 * 32 + 255) / 256, 256>>>(qw, kw, vw, sw);
            k_gemm4<<<gg4, 256, G4_SMEM>>>(qb, kb, vb, sb, Q, K, V, S, NN);
        }

        k_edge<<<(NN * 32 + 255) / 256, 256>>>(ea, ew, src);

        k_zero_bn<<<1, 128>>>();
        k_bn_reduce<<<512, 128>>>();
        k_bn_apply<<<(NN * HC + 255) / 256, 256>>>(bg, bb, (L == 0) ? x1 : x2);

        in_ptr = x1;
    }
}

// round 11
// speedup vs baseline: 1.7695x; 1.4407x over previous
#include <cuda_runtime.h>
#include <cuda_bf16.h>
#include <cstdint>
#include <math.h>

#define NN 50000
#define EE 400000
#define HC 128
#define EDIM 16
#define BN_EPS 1e-5f

// ---------------- scratch (device globals; no allocation allowed) ----------------
__device__ float g_Q[(size_t)NN * HC];
__device__ float g_K[(size_t)NN * HC];
__device__ float g_V[(size_t)NN * HC];
__device__ float g_S[(size_t)NN * HC];   // skip; overwritten with y = attn + skip

// bf16 hi/lo pre-split operands, k-quad-permuted
__device__ __nv_bfloat16 g_Ah[(size_t)NN * HC];
__device__ __nv_bfloat16 g_Al[(size_t)NN * HC];
__device__ __nv_bfloat16 g_Wth[4][HC * HC];   // W transposed: [n][k-permuted]
__device__ __nv_bfloat16 g_Wtl[4][HC * HC];

__device__ int g_deg[NN];
__device__ int g_cur[NN];
__device__ int g_off[NN + 1];
__device__ int g_eids[EE];
__device__ int g_srcs[EE];                  // src node per CSR position
__device__ float g_EAp[(size_t)EE * EDIM];  // EA permuted into CSR order
__device__ int g_bsum[256];
__device__ int g_boff[256];
__device__ float g_bnsum[HC];
__device__ float g_bnsq[HC];

// ---------------- bf16 hi/lo split helpers ----------------
__device__ __forceinline__ void bf16_split(float x, unsigned short& h, unsigned short& l) {
    __nv_bfloat16 hb = __float2bfloat16_rn(x);
    __nv_bfloat16 lb = __float2bfloat16_rn(x - __bfloat162float(hb));
    h = __bfloat16_as_ushort(hb);
    l = __bfloat16_as_ushort(lb);
}

// pre-split A [N][128] fp32 -> g_Ah/g_Al bf16 quads (k-permuted). (layer-0 input only)
__global__ void k_splitA(const float* __restrict__ A, int nthr) {
    int i = blockIdx.x * blockDim.x + threadIdx.x;
    if (i >= nthr) return;
    int row = i >> 5, qi = i & 31;
    int s = qi >> 2, t = qi & 3;
    const float* ap = A + (size_t)row * HC;
    float2 vlo = *(const float2*)&ap[16 * s + 2 * t];
    float2 vhi = *(const float2*)&ap[16 * s + 8 + 2 * t];
    unsigned short h0, l0, h1, l1, h2, l2, h3, l3;
    bf16_split(vlo.x, h0, l0);
    bf16_split(vlo.y, h1, l1);
    bf16_split(vhi.x, h2, l2);
    bf16_split(vhi.y, h3, l3);
    uint2 ph = make_uint2((unsigned)h0 | ((unsigned)h1 << 16),
                          (unsigned)h2 | ((unsigned)h3 << 16));
    uint2 pl = make_uint2((unsigned)l0 | ((unsigned)l1 << 16),
                          (unsigned)l2 | ((unsigned)l3 << 16));
    *(uint2*)&g_Ah[(size_t)row * HC + qi * 4] = ph;
    *(uint2*)&g_Al[(size_t)row * HC + qi * 4] = pl;
}

// pre-split + transpose the 4 weights: Wt[n][k-permuted] from W[k][n]
__global__ void k_splitW(const float* __restrict__ w0, const float* __restrict__ w1,
                         const float* __restrict__ w2, const float* __restrict__ w3) {
    int i = blockIdx.x * blockDim.x + threadIdx.x;   // 0 .. 4*128*32-1
    if (i >= 4 * 128 * 32) return;
    int which = i >> 12;
    int rem = i & 4095;
    int n = rem >> 5, qi = rem & 31;
    int s = qi >> 2, t = qi & 3;
    const float* w = which == 0 ? w0 : which == 1 ? w1 : which == 2 ? w2 : w3;
    float x0 = w[(size_t)(16 * s + 2 * t) * HC + n];
    float x1 = w[(size_t)(16 * s + 2 * t + 1) * HC + n];
    float x2 = w[(size_t)(16 * s + 8 + 2 * t) * HC + n];
    float x3 = w[(size_t)(16 * s + 9 + 2 * t) * HC + n];
    unsigned short h0, l0, h1, l1, h2, l2, h3, l3;
    bf16_split(x0, h0, l0);
    bf16_split(x1, h1, l1);
    bf16_split(x2, h2, l2);
    bf16_split(x3, h3, l3);
    uint2 ph = make_uint2((unsigned)h0 | ((unsigned)h1 << 16),
                          (unsigned)h2 | ((unsigned)h3 << 16));
    uint2 pl = make_uint2((unsigned)l0 | ((unsigned)l1 << 16),
                          (unsigned)l2 | ((unsigned)l3 << 16));
    *(uint2*)&g_Wth[which][(size_t)n * HC + qi * 4] = ph;
    *(uint2*)&g_Wtl[which][(size_t)n * HC + qi * 4] = pl;
}

// ---------------- CSR build ----------------
__global__ void k_zero_csr() {
    int i = blockIdx.x * blockDim.x + threadIdx.x;
    if (i < NN) { g_deg[i] = 0; g_cur[i] = 0; }
}

__global__ void k_hist(const int* __restrict__ dst) {
    int e = blockIdx.x * blockDim.x + threadIdx.x;
    if (e < EE) atomicAdd(&g_deg[dst[e]], 1);
}

__global__ void k_scan1() {
    __shared__ int sh[256];
    int tid = threadIdx.x;
    int i = blockIdx.x * 256 + tid;
    int v = (i < NN) ? g_deg[i] : 0;
    sh[tid] = v;
    __syncthreads();
    for (int o = 1; o < 256; o <<= 1) {
        int t = (tid >= o) ? sh[tid - o] : 0;
        __syncthreads();
        sh[tid] += t;
        __syncthreads();
    }
    if (i < NN) g_off[i] = sh[tid] - v;
    if (tid == 255) g_bsum[blockIdx.x] = sh[255];
}

__global__ void k_scan2(int nb) {
    __shared__ int sh[256];
    int tid = threadIdx.x;
    int v = (tid < nb) ? g_bsum[tid] : 0;
    sh[tid] = v;
    __syncthreads();
    for (int o = 1; o < 256; o <<= 1) {
        int t = (tid >= o) ? sh[tid - o] : 0;
        __syncthreads();
        sh[tid] += t;
        __syncthreads();
    }
    g_boff[tid] = sh[tid] - v;
}

__global__ void k_scan3() {
    int i = blockIdx.x * 256 + threadIdx.x;
    if (i < NN) g_off[i] += g_boff[blockIdx.x];
    if (i == 0) g_off[NN] = EE;
}

__global__ void k_fill(const int* __restrict__ dst) {
    int e = blockIdx.x * blockDim.x + threadIdx.x;
    if (e < EE) {
        int d = dst[e];
        int pos = g_off[d] + atomicAdd(&g_cur[d], 1);
        g_eids[pos] = e;
    }
}

// permute EA into CSR order + materialize srcs (kills one gather level)
__global__ void k_permEA(const float* __restrict__ EA, const int* __restrict__ src) {
    int i = blockIdx.x * blockDim.x + threadIdx.x;   // EE*4 threads
    if (i >= EE * 4) return;
    int pos = i >> 2, part = i & 3;
    int e = g_eids[pos];
    float4 v = *(const float4*)&EA[(size_t)e * EDIM + part * 4];
    *(float4*)&g_EAp[(size_t)pos * EDIM + part * 4] = v;
    if (part == 0) g_srcs[pos] = src[e];
}

// ---------------- fused bf16x2 tensor-core GEMM (Q,K,V,S in one launch) ----------------
#define SROW 80
#define PLANE (128 * SROW)
#define G4_SMEM (4 * PLANE * 2)   // 81920 bytes

__device__ __forceinline__ void cpa16(unsigned int dst, const void* src, int bytes) {
    asm volatile("cp.async.ca.shared.global [%0], [%1], 16, %2;\n"
                 :: "r"(dst), "l"(src), "r"(bytes));
}

__device__ __forceinline__ void mma16(float* d, unsigned a0, unsigned a1, unsigned a2,
                                      unsigned a3, unsigned b0, unsigned b1) {
    asm volatile(
        "mma.sync.aligned.m16n8k16.row.col.f32.bf16.bf16.f32 "
        "{%0,%1,%2,%3}, {%4,%5,%6,%7}, {%8,%9}, {%0,%1,%2,%3};\n"
        : "+f"(d[0]), "+f"(d[1]), "+f"(d[2]), "+f"(d[3])
        : "r"(a0), "r"(a1), "r"(a2), "r"(a3), "r"(b0), "r"(b1));
}

__global__ void __launch_bounds__(256, 2) k_gemm4(
    const float* __restrict__ b0p, const float* __restrict__ b1p,
    const float* __restrict__ b2p, const float* __restrict__ b3p,
    float* __restrict__ o0p, float* __restrict__ o1p,
    float* __restrict__ o2p, float* __restrict__ o3p, int M)
{
    extern __shared__ __nv_bfloat16 sm[];
    __nv_bfloat16* Ah = sm;
    __nv_bfloat16* Al = sm + PLANE;
    __nv_bfloat16* Bh = sm + 2 * PLANE;
    __nv_bfloat16* Bl = sm + 3 * PLANE;
    unsigned int Ah_u = (unsigned int)__cvta_generic_to_shared(Ah);
    unsigned int Al_u = (unsigned int)__cvta_generic_to_shared(Al);
    unsigned int Bh_u = (unsigned int)__cvta_generic_to_shared(Bh);
    unsigned int Bl_u = (unsigned int)__cvta_generic_to_shared(Bl);

    int tid = threadIdx.x;
    int wid = tid >> 5, lane = tid & 31;
    int g = lane >> 2, tig = lane & 3;
    int m0 = (wid & 1) * 64;
    int n0 = (wid >> 1) * 32;
    int brow = blockIdx.x * 128;
    int which = blockIdx.y;

    const __nv_bfloat16* Wh = &g_Wth[which][0];
    const __nv_bfloat16* Wl = &g_Wtl[which][0];
    const float* bias = which == 0 ? b0p : which == 1 ? b1p : which == 2 ? b2p : b3p;
    float* C = which == 0 ? o0p : which == 1 ? o1p : which == 2 ? o2p : o3p;

    float acc[4][4][4];
#pragma unroll
    for (int i = 0; i < 4; i++)
#pragma unroll
        for (int j = 0; j < 4; j++)
#pragma unroll
            for (int r = 0; r < 4; r++) acc[i][j][r] = 0.f;

    for (int k0 = 0; k0 < 128; k0 += 64) {
#pragma unroll
        for (int j = 0; j < 4; j++) {
            int idx = tid + j * 256;
            int row = idx >> 3;
            int c = idx & 7;
            int grow = brow + row;
            int nb = (grow < M) ? 16 : 0;
            unsigned off = (unsigned)(row * SROW + c * 8) * 2;
            cpa16(Ah_u + off, &g_Ah[(size_t)grow * HC + k0 + c * 8], nb);
            cpa16(Al_u + off, &g_Al[(size_t)grow * HC + k0 + c * 8], nb);
        }
#pragma unroll
        for (int j = 0; j < 4; j++) {
            int idx = tid + j * 256;
            int row = idx >> 3;
            int c = idx & 7;
            unsigned off = (unsigned)(row * SROW + c * 8) * 2;
            cpa16(Bh_u + off, &Wh[(size_t)row * HC + k0 + c * 8], 16);
            cpa16(Bl_u + off, &Wl[(size_t)row * HC + k0 + c * 8], 16);
        }
        asm volatile("cp.async.commit_group;\n");
        asm volatile("cp.async.wait_group 0;\n");
        __syncthreads();

#pragma unroll
        for (int ks = 0; ks < 4; ks++) {
            int kq = ks * 16 + tig * 4;
            unsigned bh[4][2], bl[4][2];
#pragma unroll
            for (int nf = 0; nf < 4; nf++) {
                int nrow = n0 + nf * 8 + g;
                uint2 vh = *(const uint2*)&Bh[nrow * SROW + kq];
                uint2 vl = *(const uint2*)&Bl[nrow * SROW + kq];
                bh[nf][0] = vh.x; bh[nf][1] = vh.y;
                bl[nf][0] = vl.x; bl[nf][1] = vl.y;
            }
#pragma unroll
            for (int mf = 0; mf < 4; mf++) {
                int ar = (m0 + mf * 16 + g) * SROW + kq;
                uint2 h0 = *(const uint2*)&Ah[ar];
                uint2 h1 = *(const uint2*)&Ah[ar + 8 * SROW];
                uint2 l0 = *(const uint2*)&Al[ar];
                uint2 l1 = *(const uint2*)&Al[ar + 8 * SROW];
#pragma unroll
                for (int nf = 0; nf < 4; nf++) {
                    float* d = acc[mf][nf];
                    mma16(d, h0.x, h1.x, h0.y, h1.y, bh[nf][0], bh[nf][1]);
                    mma16(d, h0.x, h1.x, h0.y, h1.y, bl[nf][0], bl[nf][1]);
                    mma16(d, l0.x, l1.x, l0.y, l1.y, bh[nf][0], bh[nf][1]);
                }
            }
        }
        __syncthreads();
    }

#pragma unroll
    for (int nf = 0; nf < 4; nf++) {
        int col = n0 + nf * 8 + tig * 2;
        float b0v = bias[col], b1v = bias[col + 1];
#pragma unroll
        for (int mf = 0; mf < 4; mf++) {
            int r0 = brow + m0 + mf * 16 + g;
            float* d = acc[mf][nf];
            if (r0 < M)
                *(float2*)&C[(size_t)r0 * 128 + col] = make_float2(d[0] + b0v, d[1] + b1v);
            if (r0 + 8 < M)
                *(float2*)&C[(size_t)(r0 + 8) * 128 + col] = make_float2(d[2] + b0v, d[3] + b1v);
        }
    }
}

// ---------------- edge attention v3: CSR-ordered srcs/EA + 4-edge batching ----------------
__global__ void __launch_bounds__(256) k_edge(const float* __restrict__ EW)
{
    __shared__ __align__(16) float4 ews[16 * 32];
    for (int i = threadIdx.x; i < 16 * 32; i += 256)
        ews[i] = ((const float4*)EW)[i];
    __syncthreads();

    int warp = (blockIdx.x * 256 + threadIdx.x) >> 5;
    int lane = threadIdx.x & 31;
    if (warp >= NN) return;
    int node = warp;
    int sub = lane & 7;
    int beg = g_off[node], end = g_off[node + 1];

    float4 qv = *(const float4*)&g_Q[(size_t)node * HC + lane * 4];

    // per-node setup: P[h][d] for this lane's (d0,d1) = (2*sub, 2*sub+1)
    float p0 = 0.f, p1 = 0.f;
#pragma unroll
    for (int d = 0; d < EDIM; d++) {
        float4 wc = ews[d * 32 + lane];
        float part = qv.x * wc.x + qv.y * wc.y + qv.z * wc.z + qv.w * wc.w;
        part += __shfl_xor_sync(0xffffffffu, part, 1);
        part += __shfl_xor_sync(0xffffffffu, part, 2);
        part += __shfl_xor_sync(0xffffffffu, part, 4);
        if (d == 2 * sub) p0 = part;
        if (d == 2 * sub + 1) p1 = part;
    }

    float m = -1e30f, s = 0.f;
    float ax = 0.f, ay = 0.f, az = 0.f, aw = 0.f;
    float g0 = 0.f, g1 = 0.f;

    int p = beg;
    for (; p + 4 <= end; p += 4) {
        // issue ALL loads for 4 edges first (MLP), then 4 cheap updates
        int sn[4];
#pragma unroll
        for (int j = 0; j < 4; j++) sn[j] = g_srcs[p + j];
        float2 ea[4];
#pragma unroll
        for (int j = 0; j < 4; j++)
            ea[j] = *(const float2*)&g_EAp[(size_t)(p + j) * EDIM + 2 * sub];
        float4 kv[4], vv[4];
#pragma unroll
        for (int j = 0; j < 4; j++)
            kv[j] = *(const float4*)&g_K[(size_t)sn[j] * HC + lane * 4];
#pragma unroll
        for (int j = 0; j < 4; j++)
            vv[j] = *(const float4*)&g_V[(size_t)sn[j] * HC + lane * 4];

        float a[4];
#pragma unroll
        for (int j = 0; j < 4; j++) {
            float part = qv.x * kv[j].x + qv.y * kv[j].y + qv.z * kv[j].z + qv.w * kv[j].w
                       + ea[j].x * p0 + ea[j].y * p1;
            part += __shfl_xor_sync(0xffffffffu, part, 1);
            part += __shfl_xor_sync(0xffffffffu, part, 2);
            part += __shfl_xor_sync(0xffffffffu, part, 4);
            a[j] = part * 0.17677669529663687f;
        }
#pragma unroll
        for (int j = 0; j < 4; j++) {
            float nm = fmaxf(m, a[j]);
            float sc = __expf(m - nm);
            float pe = __expf(a[j] - nm);
            s = s * sc + pe;
            ax = ax * sc + pe * vv[j].x;
            ay = ay * sc + pe * vv[j].y;
            az = az * sc + pe * vv[j].z;
            aw = aw * sc + pe * vv[j].w;
            g0 = g0 * sc + pe * ea[j].x;
            g1 = g1 * sc + pe * ea[j].y;
            m = nm;
        }
    }
    for (; p < end; p++) {
        int sn = g_srcs[p];
        float2 ea2 = *(const float2*)&g_EAp[(size_t)p * EDIM + 2 * sub];
        float4 kv = *(const float4*)&g_K[(size_t)sn * HC + lane * 4];
        float part = qv.x * kv.x + qv.y * kv.y + qv.z * kv.z + qv.w * kv.w
                   + ea2.x * p0 + ea2.y * p1;
        part += __shfl_xor_sync(0xffffffffu, part, 1);
        part += __shfl_xor_sync(0xffffffffu, part, 2);
        part += __shfl_xor_sync(0xffffffffu, part, 4);
        float a = part * 0.17677669529663687f;
        float nm = fmaxf(m, a);
        float sc = __expf(m - nm);
        float pe = __expf(a - nm);
        s = s * sc + pe;
        float4 vv = *(const float4*)&g_V[(size_t)sn * HC + lane * 4];
        ax = ax * sc + pe * vv.x;
        ay = ay * sc + pe * vv.y;
        az = az * sc + pe * vv.z;
        aw = aw * sc + pe * vv.w;
        g0 = g0 * sc + pe * ea2.x;
        g1 = g1 * sc + pe * ea2.y;
        m = nm;
    }

    // epilogue: e-contribution = G[h][:] @ EW[:, lane channels]
    float ex = 0.f, ey = 0.f, ez = 0.f, ew_ = 0.f;
    int base = lane & ~7;
#pragma unroll
    for (int j = 0; j < 8; j++) {
        float gg0 = __shfl_sync(0xffffffffu, g0, base + j);
        float gg1 = __shfl_sync(0xffffffffu, g1, base + j);
        float4 w0 = ews[(2 * j) * 32 + lane];
        float4 w1 = ews[(2 * j + 1) * 32 + lane];
        ex += gg0 * w0.x + gg1 * w1.x;
        ey += gg0 * w0.y + gg1 * w1.y;
        ez += gg0 * w0.z + gg1 * w1.z;
        ew_ += gg0 * w0.w + gg1 * w1.w;
    }

    float inv = (end > beg) ? (1.f / s) : 0.f;
    size_t o = (size_t)node * HC + lane * 4;
    float4 sv = *(const float4*)&g_S[o];
    float4 y = make_float4((ax + ex) * inv + sv.x, (ay + ey) * inv + sv.y,
                           (az + ez) * inv + sv.z, (aw + ew_) * inv + sv.w);
    *(float4*)&g_S[o] = y;
}

// ---------------- batchnorm + relu ----------------
__global__ void k_zero_bn() {
    int t = threadIdx.x;
    if (t < HC) { g_bnsum[t] = 0.f; g_bnsq[t] = 0.f; }
}

__global__ void k_bn_reduce() {
    int c = threadIdx.x;
    float sum = 0.f, sq = 0.f;
    for (int n = blockIdx.x; n < NN; n += gridDim.x) {
        float v = g_S[(size_t)n * HC + c];
        sum += v; sq += v * v;
    }
    atomicAdd(&g_bnsum[c], sum);
    atomicAdd(&g_bnsq[c], sq);
}

// bn+relu; optionally also emit bf16 hi/lo split (k-quad permuted) for next layer's GEMM
__global__ void k_bn_apply(const float* __restrict__ gamma,
                           const float* __restrict__ beta,
                           float* __restrict__ out, int do_split)
{
    int i = blockIdx.x * blockDim.x + threadIdx.x;
    if (i >= NN * HC) return;
    int c = i & 127;
    int n = i >> 7;
    float mean = g_bnsum[c] * (1.f / NN);
    float var = fmaf(-mean, mean, g_bnsq[c] * (1.f / NN));
    float v = (g_S[i] - mean) * rsqrtf(var + BN_EPS) * gamma[c] + beta[c];
    float r = fmaxf(v, 0.f);
    out[i] = r;
    if (do_split) {
        int s = c >> 4, r15 = c & 15;
        int t, pq;
        if (r15 < 8) { t = r15 >> 1; pq = r15 & 1; }
        else { t = (r15 - 8) >> 1; pq = 2 + (r15 & 1); }
        int pos = s * 16 + t * 4 + pq;
        unsigned short h, l;
        bf16_split(r, h, l);
        g_Ah[(size_t)n * HC + pos] = __ushort_as_bfloat16(h);
        g_Al[(size_t)n * HC + pos] = __ushort_as_bfloat16(l);
    }
}

// ---------------- driver ----------------
extern "C" void kernel_launch(void* const* d_in, const int* in_sizes, int n_in,
                              void* d_out, int out_size)
{
    const float* x  = (const float*)d_in[0];
    const int*   ei = (const int*)d_in[1];
    const float* ea = (const float*)d_in[2];
    const int* src = ei;
    const int* dst = ei + EE;

    float* out = (float*)d_out;
    float* x1 = out;
    float* x2 = out + (size_t)NN * HC;

    float *Q, *K, *V, *S;
    cudaGetSymbolAddress((void**)&Q, g_Q);
    cudaGetSymbolAddress((void**)&K, g_K);
    cudaGetSymbolAddress((void**)&V, g_V);
    cudaGetSymbolAddress((void**)&S, g_S);

    cudaFuncSetAttribute(k_gemm4, cudaFuncAttributeMaxDynamicSharedMemorySize, G4_SMEM);

    const int NB1 = (NN + 255) / 256;
    const dim3 gg4((NN + 127) / 128, 4);
    const int nthrA = NN * 32;

    for (int L = 0; L < 2; L++) {
        int b = 3 + L * 11;
        const float* qw = (const float*)d_in[b + 0];
        const float* qb = (const float*)d_in[b + 1];
        const float* kw = (const float*)d_in[b + 2];
        const float* kb = (const float*)d_in[b + 3];
        const float* vw = (const float*)d_in[b + 4];
        const float* vb = (const float*)d_in[b + 5];
        const float* sw = (const float*)d_in[b + 7];
        const float* sb = (const float*)d_in[b + 8];
        const float* bg = (const float*)d_in[b + 9];
        const float* bb = (const float*)d_in[b + 10];
        const float* ew = (const float*)d_in[b + 6];

        if (L == 0) {
            k_splitA<<<(nthrA + 255) / 256, 256>>>(x, nthrA);                      // 0
            k_splitW<<<(4 * 128 * 32 + 255) / 256, 256>>>(qw, kw, vw, sw);         // 1
            k_zero_csr<<<NB1, 256>>>();                                            // 2
            k_hist<<<(EE + 255) / 256, 256>>>(dst);                                // 3
            k_scan1<<<NB1, 256>>>();                                               // 4
            k_gemm4<<<gg4, 256, G4_SMEM>>>(qb, kb, vb, sb, Q, K, V, S, NN);        // 5 (profile target)
            k_scan2<<<1, 256>>>(NB1);
            k_scan3<<<NB1, 256>>>();
            k_fill<<<(EE + 255) / 256, 256>>>(dst);
            k_permEA<<<(EE * 4 + 255) / 256, 256>>>(ea, src);
        } else {
            k_splitW<<<(4 * 128 * 32 + 255) / 256, 256>>>(qw, kw, vw, sw);
            k_gemm4<<<gg4, 256, G4_SMEM>>>(qb, kb, vb, sb, Q, K, V, S, NN);
        }

        k_edge<<<(NN * 32 + 255) / 256, 256>>>(ew);

        k_zero_bn<<<1, 128>>>();
        k_bn_reduce<<<512, 128>>>();
        k_bn_apply<<<(NN * HC + 255) / 256, 256>>>(bg, bb, (L == 0) ? x1 : x2,
                                                   (L == 0) ? 1 : 0);
    }
}